// round 12
// baseline (speedup 1.0000x reference)
#include <cuda_runtime.h>
#include <cuda_bf16.h>
#include <math.h>
#include <stdint.h>

#define G1 4.0f
#define EPSL 1e-10f

// ---------------- scratch (device globals) ----------------------------------
__device__ float    g_sT[40u*75u*2048u];      // [b][t][r]: s scores
__device__ float    g_rsmax[40u*5u*2048u];    // [b][seg][r] row max
__device__ float    g_rsinv[40u*5u*2048u];    // [b][seg][r] 1/sumexp
__device__ float    g_cinv_nt[40*75];
__device__ float    g_sd[40*8*75];
__device__ uint32_t g_aH[40u*75u*1024u];      // alpha numerators, bf16-hi pairs
__device__ uint32_t g_aL[40u*75u*1024u];      // alpha numerators, bf16-lo pairs
__device__ uint32_t g_eh[8*75*128];           // text bf16-hi pairs
__device__ uint32_t g_el2[8*75*128];          // text bf16-lo pairs
__device__ float    g_vtp[8u*40u*75u*256u];   // split-K partials of v_tidal
__device__ float    g_vns[40*8*256];
__device__ float    g_el[40*75];
__device__ float    g_logit2[40*8*5];
__device__ float    g_regval[40];

// ---------------- helpers ----------------------------------------------------
__device__ __forceinline__ uint32_t s2u(const void* p) {
    uint32_t a;
    asm("{ .reg .u64 t; cvta.to.shared.u64 t, %1; cvt.u32.u64 %0, t; }" : "=r"(a) : "l"(p));
    return a;
}
__device__ __forceinline__ void cp16(uint32_t dst, const void* src) {
    asm volatile("cp.async.cg.shared.global [%0], [%1], 16;" :: "r"(dst), "l"(src));
}
__device__ __forceinline__ void cp_commit() { asm volatile("cp.async.commit_group;" ::: "memory"); }
__device__ __forceinline__ void cp_wait0()  { asm volatile("cp.async.wait_group 0;" ::: "memory"); }

__device__ __forceinline__ void ldm_x4(uint32_t& r0, uint32_t& r1, uint32_t& r2,
                                       uint32_t& r3, uint32_t addr) {
    asm volatile("ldmatrix.sync.aligned.m8n8.x4.shared.b16 {%0,%1,%2,%3}, [%4];"
                 : "=r"(r0), "=r"(r1), "=r"(r2), "=r"(r3) : "r"(addr));
}
__device__ __forceinline__ void ldm_x4_t(uint32_t& r0, uint32_t& r1, uint32_t& r2,
                                         uint32_t& r3, uint32_t addr) {
    asm volatile("ldmatrix.sync.aligned.m8n8.x4.trans.shared.b16 {%0,%1,%2,%3}, [%4];"
                 : "=r"(r0), "=r"(r1), "=r"(r2), "=r"(r3) : "r"(addr));
}
__device__ __forceinline__ void mma_bf16(float* c, uint32_t a0, uint32_t a1,
                                         uint32_t a2, uint32_t a3,
                                         uint32_t b0, uint32_t b1) {
    asm volatile(
        "mma.sync.aligned.m16n8k16.row.col.f32.bf16.bf16.f32 "
        "{%0,%1,%2,%3}, {%4,%5,%6,%7}, {%8,%9}, {%0,%1,%2,%3};"
        : "+f"(c[0]), "+f"(c[1]), "+f"(c[2]), "+f"(c[3])
        : "r"(a0), "r"(a1), "r"(a2), "r"(a3), "r"(b0), "r"(b1));
}
// fast split: x,y -> packed bf16 hi + packed bf16 lo residual
__device__ __forceinline__ void bsplit2(float x, float y, uint32_t& hi, uint32_t& lo) {
    uint32_t h;
    asm("cvt.rn.bf16x2.f32 %0, %1, %2;" : "=r"(h) : "f"(y), "f"(x));
    float hx = __uint_as_float(h << 16);
    float hy = __uint_as_float(h & 0xFFFF0000u);
    float lx = x - hx, ly = y - hy;
    asm("cvt.rn.bf16x2.f32 %0, %1, %2;" : "=r"(lo) : "f"(ly), "f"(lx));
    hi = h;
}

// phase1 per-stage 30208 B: AH[32 k][272 B] @0 | AL @8704 | BH[80][20w] @17408 | BL @23808
#define P1_ST  30208
#define P1_SZ  60416
// vtidal: per-stage 33280 B: AH[80][20] @0 | AL @6400 | BH[128][20] @12800 | BL @23040
#define P3_ST  33280
#define P3_SZ  66560

// ============ PHASE 0: convert text to bf16 hi/lo pairs =====================
__global__ void __launch_bounds__(256) k_prep(const float* __restrict__ text) {
    int i = blockIdx.x * 256 + threadIdx.x;   // 76800 pairs
    float2 v = *(const float2*)(text + 2 * i);
    uint32_t h, l;
    bsplit2(v.x, v.y, h, l);
    g_eh[i] = h; g_el2[i] = l;
}

// ============ PHASE 1: pipelined mma gemm_s (640 blks) ======================
__global__ void __launch_bounds__(256) k_phase1(const float* __restrict__ image,
                                                const float* __restrict__ text) {
    extern __shared__ __align__(16) char dsm[];
    const int bx = blockIdx.x;
    const int tid = threadIdx.x;
    const int wid = tid >> 5, lane = tid & 31;

    const int b  = bx >> 4;
    const int rb = bx & 15;
    const int r0 = rb * 128;
    const int m  = rb >> 1, p0 = (rb & 1) * 128;
    const float* srcA = image + (size_t)(b * 8 + m) * 65536;
    const uint32_t* eH = g_eh  + (size_t)(b / 5) * 9600;
    const uint32_t* eL = g_el2 + (size_t)(b / 5) * 9600;
    const uint32_t sbase = s2u(dsm);
    const int gid = lane >> 2, tig = lane & 3;

    // zero B pad rows 75..79 in both stages
    for (int i = tid; i < 100; i += 256) {
        #pragma unroll
        for (int s = 0; s < 2; s++) {
            *(uint32_t*)(dsm + s * P1_ST + 17408 + (1500 + i) * 4) = 0;
            *(uint32_t*)(dsm + s * P1_ST + 23808 + (1500 + i) * 4) = 0;
        }
    }

    float4 iv[4];
    auto load_a = [&](int c) {
        const int kb = c * 32;
        #pragma unroll
        for (int it = 0; it < 4; it++) {
            int lin = tid + it * 256;
            int k = lin >> 5, f4 = (lin & 31) * 4;
            iv[it] = *(const float4*)(srcA + (size_t)(kb + k) * 256 + p0 + f4);
        }
    };
    // convert in regs, store bf16 hi/lo to [k][p] tile (272 B rows)
    auto store_a = [&](int s) {
        char* AH = dsm + s * P1_ST;
        char* AL = AH + 8704;
        #pragma unroll
        for (int it = 0; it < 4; it++) {
            int lin = tid + it * 256;
            int k = lin >> 5, p4 = (lin & 31) * 4;
            uint32_t h0, l0, h1, l1;
            bsplit2(iv[it].x, iv[it].y, h0, l0);
            bsplit2(iv[it].z, iv[it].w, h1, l1);
            int off = k * 272 + p4 * 2;
            *(uint2*)(AH + off) = make_uint2(h0, h1);
            *(uint2*)(AL + off) = make_uint2(l0, l1);
        }
    };
    auto stage_b = [&](int c, int s) {
        const int kw = c * 16;
        #pragma unroll
        for (int i = 0; i < 3; i++) {
            int idx = tid + i * 256;
            if (idx < 600) {
                int half = (idx >= 300) ? 1 : 0;
                int j = idx - half * 300;
                int t = j >> 2, c4 = (j & 3) * 4;
                const uint32_t* src = (half ? eL : eH) + t * 128 + kw + c4;
                cp16(sbase + s * P1_ST + 17408 + half * 6400 + (t * 20 + c4) * 4, src);
            }
        }
        cp_commit();
    };

    float acc[10][4];
    #pragma unroll
    for (int nt = 0; nt < 10; nt++)
        #pragma unroll
        for (int q = 0; q < 4; q++) acc[nt][q] = 0.f;

    // ldmatrix.trans A base: lanes -> k-rows, matrices -> (m-half, k-half)
    const uint32_t aoffT = (uint32_t)(((lane & 7) + ((lane >> 4) & 1) * 8) * 272
                                      + ((lane >> 3) & 1) * 16 + wid * 32);
    const uint32_t boff0 = (uint32_t)((((lane >> 4) & 1) * 8 + (lane & 7)) * 80
                                      + ((lane >> 3) & 1) * 16);

    // prologue: chunk 0
    load_a(0);
    stage_b(0, 0);
    store_a(0);
    cp_wait0();
    __syncthreads();

    for (int c = 0; c < 8; c++) {
        const int s = c & 1;
        if (c < 7) { load_a(c + 1); stage_b(c + 1, s ^ 1); }
        // ---- mma on stage s ------------------------------------------
        {
            const uint32_t pAH = sbase + s * P1_ST;
            const uint32_t pAL = pAH + 8704;
            const uint32_t pBH = pAH + 17408;
            const uint32_t pBL = pAH + 23808;
            #pragma unroll
            for (int ks = 0; ks < 2; ks++) {
                uint32_t ah0, ah1, ah2, ah3, al0, al1, al2, al3;
                ldm_x4_t(ah0, ah1, ah2, ah3, pAH + aoffT + ks * 4352);
                ldm_x4_t(al0, al1, al2, al3, pAL + aoffT + ks * 4352);
                #pragma unroll
                for (int j = 0; j < 5; j++) {
                    uint32_t bh0, bh1, bh2, bh3, bl0, bl1, bl2, bl3;
                    uint32_t bo = boff0 + (uint32_t)(j * 16 * 80 + ks * 32);
                    ldm_x4(bh0, bh1, bh2, bh3, pBH + bo);
                    ldm_x4(bl0, bl1, bl2, bl3, pBL + bo);
                    mma_bf16(acc[2 * j],     ah0, ah1, ah2, ah3, bh0, bh1);
                    mma_bf16(acc[2 * j + 1], ah0, ah1, ah2, ah3, bh2, bh3);
                    mma_bf16(acc[2 * j],     ah0, ah1, ah2, ah3, bl0, bl1);
                    mma_bf16(acc[2 * j + 1], ah0, ah1, ah2, ah3, bl2, bl3);
                    mma_bf16(acc[2 * j],     al0, al1, al2, al3, bh0, bh1);
                    mma_bf16(acc[2 * j + 1], al0, al1, al2, al3, bh2, bh3);
                }
            }
        }
        if (c < 7) { store_a(s ^ 1); cp_wait0(); }
        __syncthreads();
    }
    // ---- epilogue: stage C to sc[t][132 r] --------------------------
    float* sc = (float*)dsm;
    const int rA = wid * 16 + gid;
    #pragma unroll
    for (int nt = 0; nt < 10; nt++) {
        int t0 = nt * 8 + tig * 2;
        sc[t0 * 132 + rA]           = acc[nt][0];
        sc[(t0 + 1) * 132 + rA]     = acc[nt][1];
        sc[t0 * 132 + rA + 8]       = acc[nt][2];
        sc[(t0 + 1) * 132 + rA + 8] = acc[nt][3];
    }
    __syncthreads();
    if (tid < 128) {
        const int r = tid;
        #pragma unroll
        for (int seg = 0; seg < 5; seg++) {
            float mx = -3.4e38f;
            #pragma unroll
            for (int l = 0; l < 15; l++)
                mx = fmaxf(mx, sc[(seg * 15 + l) * 132 + r]);
            float se = 0.f;
            #pragma unroll
            for (int l = 0; l < 15; l++)
                se += __expf(sc[(seg * 15 + l) * 132 + r] - mx);
            size_t off = ((size_t)b * 5 + seg) * 2048 + r0 + r;
            g_rsmax[off] = mx;
            g_rsinv[off] = 1.0f / se;
        }
    }
    for (int i = tid; i < 9600; i += 256) {
        int t = i >> 7, r = i & 127;
        g_sT[((size_t)b * 75 + t) * 2048 + r0 + r] = sc[t * 132 + r];
    }
}

// ============ PHASE 2: colstats (3000) + vns (320) ===========================
__global__ void __launch_bounds__(256) k_colstats(const float* __restrict__ image) {
    const int bx = blockIdx.x;
    const int tid = threadIdx.x, lane = tid & 31, w = tid >> 5;
    __shared__ float sred[256];

    if (bx >= 3000) {
        // -------- vns from image (overlaps exp-bound colstats) ---------------
        const int bm = bx - 3000;
        const float* src = image + (size_t)bm * 65536;
        float* invn = sred;
        float s0 = 0.f, s1 = 0.f, s2 = 0.f, s3 = 0.f;
        for (int d = 0; d < 256; d += 4) {
            float x0 = src[(size_t)(d + 0) * 256 + tid];
            float x1 = src[(size_t)(d + 1) * 256 + tid];
            float x2 = src[(size_t)(d + 2) * 256 + tid];
            float x3 = src[(size_t)(d + 3) * 256 + tid];
            s0 = fmaf(x0, x0, s0); s1 = fmaf(x1, x1, s1);
            s2 = fmaf(x2, x2, s2); s3 = fmaf(x3, x3, s3);
        }
        invn[tid] = 1.0f / fmaxf(sqrtf((s0 + s1) + (s2 + s3)), 1e-12f);
        __syncthreads();
        for (int j = 0; j < 32; j++) {
            int d = w * 32 + j;
            const float* row = src + (size_t)d * 256;
            float a = 0.f;
            #pragma unroll
            for (int q = 0; q < 8; q++) {
                int p = lane + 32 * q;
                a = fmaf(row[p], invn[p], a);
            }
            #pragma unroll
            for (int o = 16; o > 0; o >>= 1) a += __shfl_xor_sync(0xffffffffu, a, o);
            if (lane == 0) g_vns[(size_t)bm * 256 + d] = a;
        }
        return;
    }

    const int b = bx / 75, t = bx % 75, seg = t / 15;
    const float* col = g_sT + ((size_t)b * 75 + t) * 2048;

    float vals[8];
    *(float4*)vals       = *(const float4*)(col + tid * 8);
    *(float4*)(vals + 4) = *(const float4*)(col + tid * 8 + 4);

    float mx = vals[0];
    #pragma unroll
    for (int k = 1; k < 8; k++) mx = fmaxf(mx, vals[k]);
    #pragma unroll
    for (int o = 16; o > 0; o >>= 1) mx = fmaxf(mx, __shfl_xor_sync(0xffffffffu, mx, o));
    if (lane == 0) sred[w] = mx;
    __syncthreads();
    float cmax = sred[0];
    #pragma unroll
    for (int q = 1; q < 8; q++) cmax = fmaxf(cmax, sred[q]);

    // SoA rowstats: vectorized loads
    float mxv[8], inv[8];
    {
        const size_t off = ((size_t)b * 5 + seg) * 2048 + tid * 8;
        *(float4*)mxv       = *(const float4*)(g_rsmax + off);
        *(float4*)(mxv + 4) = *(const float4*)(g_rsmax + off + 4);
        *(float4*)inv       = *(const float4*)(g_rsinv + off);
        *(float4*)(inv + 4) = *(const float4*)(g_rsinv + off + 4);
    }

    float e1[8], al[8];
    float sraw = 0.f, snt = 0.f;
    #pragma unroll
    for (int k = 0; k < 8; k++) {
        e1[k] = __expf(vals[k] - cmax);
        sraw += e1[k];
        al[k] = __expf(G1 * __expf(vals[k] - mxv[k]) * inv[k]);
        snt += al[k];
    }
    {
        uint32_t* aH = g_aH + (size_t)b * 76800 + t * 1024 + tid * 4;
        uint32_t* aL = g_aL + (size_t)b * 76800 + t * 1024 + tid * 4;
        #pragma unroll
        for (int j = 0; j < 4; j++) {
            uint32_t h, l;
            bsplit2(al[2 * j], al[2 * j + 1], h, l);
            aH[j] = h; aL[j] = l;
        }
    }
    float sr = sraw, sn = snt;
    #pragma unroll
    for (int o = 16; o > 0; o >>= 1) {
        sr += __shfl_xor_sync(0xffffffffu, sr, o);
        sn += __shfl_xor_sync(0xffffffffu, sn, o);
    }
    if (lane == 0) { sred[8 + w] = sr; sred[16 + w] = sn; }
    __syncthreads();
    float tot = 0.f;
    #pragma unroll
    for (int q = 0; q < 8; q++) tot += sred[8 + q];
    const float cinv = 1.0f / tot;
    if (tid == 0) {
        float s = 0.f;
        #pragma unroll
        for (int q = 0; q < 8; q++) s += sred[16 + q];
        g_cinv_nt[b * 75 + t] = 1.0f / s;
    }
    float e2 = 0.f;
    #pragma unroll
    for (int k = 0; k < 8; k++) e2 += __expf(e1[k] * cinv);
    #pragma unroll
    for (int o = 16; o > 0; o >>= 1) e2 += __shfl_xor_sync(0xffffffffu, e2, o);
    if (lane == 0) g_sd[((size_t)b * 8 + w) * 75 + t] = e2;
}

// ============ PHASE 3: mma v_tidal (640) + logit2 (320) + reg (40) ===========
__global__ void __launch_bounds__(256) k_vtidal(const float* __restrict__ image,
                                                const float* __restrict__ text) {
    extern __shared__ __align__(16) char dsm[];
    __shared__ float scv[80];
    const int bx = blockIdx.x;
    const int tid = threadIdx.x;
    const int wid = tid >> 5, lane = tid & 31;

    if (bx >= 640) {
        float* pool = (float*)dsm;
        if (bx < 960) {
            // ---- logit2 (overlaps tensor-bound vtidal) ----------------------
            const int idx = bx - 640;
            const int b = idx >> 3, m = idx & 7, blk = b / 5;
            float* shsd = pool;
            float* wred = pool + 16;
            const float vv = g_vns[((size_t)b * 8 + m) * 256 + tid];
            for (int sb = 0; sb < 5; sb++) {
                if (tid < 15) shsd[tid] = g_sd[((size_t)b * 8 + m) * 75 + sb * 15 + tid];
                __syncthreads();
                float segsum = 0.f;
                #pragma unroll
                for (int l = 0; l < 15; l++) segsum += shsd[l];
                float em = 0.f;
                #pragma unroll
                for (int l = 0; l < 15; l++)
                    em = fmaf(shsd[l], text[((size_t)blk * 75 + sb * 15 + l) * 256 + tid], em);
                em /= segsum;
                float p = em * em, q = em * vv;
                #pragma unroll
                for (int o = 16; o > 0; o >>= 1) {
                    p += __shfl_xor_sync(0xffffffffu, p, o);
                    q += __shfl_xor_sync(0xffffffffu, q, o);
                }
                if (lane == 0) { wred[wid] = p; wred[8 + wid] = q; }
                __syncthreads();
                if (tid == 0) {
                    float s1 = 0.f, s2 = 0.f;
                    #pragma unroll
                    for (int j = 0; j < 8; j++) { s1 += wred[j]; s2 += wred[8 + j]; }
                    g_logit2[((size_t)b * 8 + m) * 5 + sb] =
                        s2 / (fmaxf(sqrtf(s1), 1e-12f) * 256.0f);
                }
                __syncthreads();
            }
        } else {
            // ---- beta decorrelation regularizer -----------------------------
            const int b = bx - 960;
            float* ssd   = pool;
            float* sseg  = pool + 600;
            float* sbeta = pool + 640;
            float* red   = pool + 1240;
            for (int i = tid; i < 600; i += 256) ssd[i] = g_sd[(size_t)b * 600 + i];
            __syncthreads();
            if (tid < 40) {
                int m = tid / 5, sb2 = tid % 5;
                float s = 0.f;
                for (int l = 0; l < 15; l++) s += ssd[m * 75 + sb2 * 15 + l];
                sseg[tid] = s;
            }
            __syncthreads();
            for (int i = tid; i < 600; i += 256) {
                int m = i / 75, t = i % 75;
                sbeta[i] = ssd[i] / sseg[m * 5 + t / 15];
            }
            __syncthreads();
            float p = 0.f;
            if (tid < 64) {
                int m = tid >> 3, n = tid & 7;
                if (m != n) {
                    float a = 0.f;
                    for (int t = 0; t < 75; t++)
                        a = fmaf(sbeta[m * 75 + t], sbeta[n * 75 + t], a);
                    p = a * a;
                }
            }
            red[tid] = p; __syncthreads();
            for (int o = 128; o > 0; o >>= 1) {
                if (tid < o) red[tid] += red[tid + o];
                __syncthreads();
            }
            if (tid == 0) g_regval[b] = sqrtf(red[0]);
        }
        return;
    }

    const int b  = bx >> 4;
    const int kz = (bx >> 1) & 7;
    const int nh = bx & 1;
    const int gid = lane >> 2, tig = lane & 3;
    const uint32_t sbase = s2u(dsm);
    const uint32_t* aHg = g_aH + (size_t)b * 76800;
    const uint32_t* aLg = g_aL + (size_t)b * 76800;
    const float* srcB = image + (size_t)(b * 8 + kz) * 65536 + (size_t)(nh * 128) * 256;

    if (tid < 75) scv[tid] = g_cinv_nt[b * 75 + tid];
    // zero A pad rows 75..79 in both stages
    for (int i = tid; i < 100; i += 256) {
        #pragma unroll
        for (int s = 0; s < 2; s++) {
            *(uint32_t*)(dsm + s * P3_ST +        (1500 + i) * 4) = 0;
            *(uint32_t*)(dsm + s * P3_ST + 6400 + (1500 + i) * 4) = 0;
        }
    }

    auto stage_a = [&](int c, int s) {
        const int rgw = (kz * 256 + c * 32) >> 1;
        #pragma unroll
        for (int i = 0; i < 3; i++) {
            int idx = tid + i * 256;
            if (idx < 600) {
                int half = (idx >= 300) ? 1 : 0;
                int j = idx - half * 300;
                int t = j >> 2, c4 = (j & 3) * 4;
                const uint32_t* src = (half ? aLg : aHg) + t * 1024 + rgw + c4;
                cp16(sbase + s * P3_ST + half * 6400 + (t * 20 + c4) * 4, src);
            }
        }
        cp_commit();
    };

    float4 vb[4];
    auto load_b = [&](int c) {
        const int p0 = c * 32;
        #pragma unroll
        for (int it = 0; it < 4; it++) {
            int idx = tid + it * 256;
            int d = idx >> 3, c4 = (idx & 7) * 4;
            vb[it] = *(const float4*)(srcB + (size_t)d * 256 + p0 + c4);
        }
    };
    auto store_b = [&](int s) {
        uint32_t* BH = (uint32_t*)(dsm + s * P3_ST + 12800);
        uint32_t* BL = (uint32_t*)(dsm + s * P3_ST + 23040);
        #pragma unroll
        for (int it = 0; it < 4; it++) {
            int idx = tid + it * 256;
            int d = idx >> 3, c4 = (idx & 7) * 4;
            uint32_t h0, l0, h1, l1;
            bsplit2(vb[it].x, vb[it].y, h0, l0);
            bsplit2(vb[it].z, vb[it].w, h1, l1);
            int w0 = d * 20 + (c4 >> 1);
            BH[w0] = h0; BH[w0 + 1] = h1;
            BL[w0] = l0; BL[w0 + 1] = l1;
        }
    };

    float acc[5][2][4];
    #pragma unroll
    for (int mt = 0; mt < 5; mt++)
        #pragma unroll
        for (int nt = 0; nt < 2; nt++)
            #pragma unroll
            for (int q = 0; q < 4; q++) acc[mt][nt][q] = 0.f;

    // prologue: chunk 0
    stage_a(0, 0);
    load_b(0);
    store_b(0);
    cp_wait0();
    __syncthreads();

    const int n0 = wid * 16;
    const uint32_t aoffb = (uint32_t)((lane & 15) * 80 + (lane >> 4) * 16);
    const uint32_t boff0 = (uint32_t)((n0 + ((lane >> 4) & 1) * 8 + (lane & 7)) * 80
                                      + ((lane >> 3) & 1) * 16);

    for (int c = 0; c < 8; c++) {
        const int s = c & 1;
        if (c < 7) { stage_a(c + 1, s ^ 1); load_b(c + 1); }
        // ---- mma on stage s (interleaved accumulators) -------------------
        {
            const uint32_t pAH = sbase + s * P3_ST;
            const uint32_t pAL = pAH + 6400;
            const uint32_t pBH = pAH + 12800;
            const uint32_t pBL = pAH + 23040;
            #pragma unroll
            for (int ks = 0; ks < 2; ks++) {
                uint32_t bh0, bh1, bh2, bh3, bl0, bl1, bl2, bl3;
                ldm_x4(bh0, bh1, bh2, bh3, pBH + boff0 + ks * 32);
                ldm_x4(bl0, bl1, bl2, bl3, pBL + boff0 + ks * 32);
                #pragma unroll
                for (int mt = 0; mt < 5; mt++) {
                    uint32_t ah0, ah1, ah2, ah3, al0, al1, al2, al3;
                    uint32_t ao = aoffb + (uint32_t)(mt * 16 * 80 + ks * 32);
                    ldm_x4(ah0, ah1, ah2, ah3, pAH + ao);
                    ldm_x4(al0, al1, al2, al3, pAL + ao);
                    mma_bf16(acc[mt][0], ah0, ah1, ah2, ah3, bh0, bh1);
                    mma_bf16(acc[mt][1], ah0, ah1, ah2, ah3, bh2, bh3);
                    mma_bf16(acc[mt][0], ah0, ah1, ah2, ah3, bl0, bl1);
                    mma_bf16(acc[mt][1], ah0, ah1, ah2, ah3, bl2, bl3);
                    mma_bf16(acc[mt][0], al0, al1, al2, al3, bh0, bh1);
                    mma_bf16(acc[mt][1], al0, al1, al2, al3, bh2, bh3);
                }
            }
        }
        if (c < 7) { store_b(s ^ 1); cp_wait0(); }
        __syncthreads();
    }
    // ---- epilogue: scale by cinv[t], write split-K partials -----------------
    float* outp = g_vtp + (size_t)kz * 40 * 75 * 256 + (size_t)b * 75 * 256 + nh * 128;
    #pragma unroll
    for (int mt = 0; mt < 5; mt++) {
        int t = mt * 16 + gid;
        #pragma unroll
        for (int nt = 0; nt < 2; nt++) {
            int d = n0 + nt * 8 + tig * 2;
            if (t < 75) {
                float ci = scv[t];
                float2 v0 = {acc[mt][nt][0] * ci, acc[mt][nt][1] * ci};
                *(float2*)(outp + (size_t)t * 256 + d) = v0;
            }
            if (t + 8 < 75) {
                float ci = scv[t + 8];
                float2 v1 = {acc[mt][nt][2] * ci, acc[mt][nt][3] * ci};
                *(float2*)(outp + (size_t)(t + 8) * 256 + d) = v1;
            }
        }
    }
}

// ============ PHASE 4: score1 only (375 blocks) =============================
__global__ void __launch_bounds__(256) k_tail(const float* __restrict__ text) {
    const int tid = threadIdx.x;
    const int lane = tid & 31, w = tid >> 5;
    const int gt = blockIdx.x * 8 + w;
    if (gt < 3000) {
        const int b = gt / 75, t = gt % 75, blk = b / 5;
        const size_t SL = (size_t)40 * 75 * 256;
        const size_t voff = ((size_t)b * 75 + t) * 256;
        const float* e = text + ((size_t)blk * 75 + t) * 256;
        float dot = 0.f, nv = 0.f, ne = 0.f;
        #pragma unroll
        for (int j = 0; j < 8; j++) {
            int d = lane + 32 * j;
            float a = 0.f;
            #pragma unroll
            for (int s8 = 0; s8 < 8; s8++) a += g_vtp[s8 * SL + voff + d];
            float cc = e[d];
            dot = fmaf(a, cc, dot); nv = fmaf(a, a, nv); ne = fmaf(cc, cc, ne);
        }
        #pragma unroll
        for (int o = 16; o > 0; o >>= 1) {
            dot += __shfl_xor_sync(0xffffffffu, dot, o);
            nv  += __shfl_xor_sync(0xffffffffu, nv,  o);
            ne  += __shfl_xor_sync(0xffffffffu, ne,  o);
        }
        if (lane == 0)
            g_el[b * 75 + t] = __expf(dot / (fmaxf(sqrtf(nv), 1e-12f) * fmaxf(sqrtf(ne), 1e-12f)));
    }
}

// ============ PHASE 5: final scalar =========================================
__global__ void k_final(float* __restrict__ out) {
    const int tid = threadIdx.x;
    __shared__ float lsm[200];
    __shared__ float bscore[8];
    if (tid < 200) {
        int blk = tid / 25, rem = tid % 25, i = rem / 5, sb = rem % 5;
        int gi = blk * 5 + i;
        float s2 = 0.f;
        #pragma unroll
        for (int m = 0; m < 8; m++) s2 += __expf(g_logit2[((size_t)gi * 8 + m) * 5 + sb]);
        float s1 = 0.f;
        #pragma unroll
        for (int l = 0; l < 15; l++) s1 += g_el[gi * 75 + sb * 15 + l];
        float l1 = __logf(__powf(s1, 0.2f) + EPSL);
        float l2 = __logf(__powf(s2, 0.2f) + EPSL);
        lsm[tid] = 10.0f * (l1 + l2);
    }
    __syncthreads();
    if (tid < 8) {
        const float* L = lsm + tid * 25;
        float rows[5] = {0, 0, 0, 0, 0}, cols[5] = {0, 0, 0, 0, 0};
        for (int i = 0; i < 5; i++)
            for (int sb = 0; sb < 5; sb++) {
                rows[i] += L[i * 5 + sb];
                cols[sb] += L[i * 5 + sb];
            }
        float acc = 0.f;
        for (int i = 0; i < 5; i++) {
            float dg = L[i * 5 + i];
            acc += -__logf(dg / rows[i] + EPSL) - __logf(dg / cols[i] + EPSL);
        }
        float reg = 0.f;
        for (int i = 0; i < 5; i++) reg += g_regval[tid * 5 + i];
        bscore[tid] = acc / 5.0f + reg / 5.0f;
    }
    __syncthreads();
    if (tid == 0) {
        float tot = 0.f;
        for (int k = 0; k < 8; k++) tot += bscore[k];
        out[0] = tot / 9.0f;
    }
}

// ---------------- launch -----------------------------------------------------
extern "C" void kernel_launch(void* const* d_in, const int* in_sizes, int n_in,
                              void* d_out, int out_size) {
    (void)in_sizes; (void)n_in; (void)out_size;
    const float* image = (const float*)d_in[0];
    const float* text  = (const float*)d_in[1];
    float* out = (float*)d_out;

    cudaFuncSetAttribute(k_phase1, cudaFuncAttributeMaxDynamicSharedMemorySize, P1_SZ);
    cudaFuncSetAttribute(k_vtidal, cudaFuncAttributeMaxDynamicSharedMemorySize, P3_SZ);

    k_prep<<<300, 256>>>(text);
    k_phase1<<<640, 256, P1_SZ>>>(image, text);
    k_colstats<<<3320, 256>>>(image);
    k_vtidal<<<1000, 256, P3_SZ>>>(image, text);
    k_tail<<<375, 256>>>(text);
    k_final<<<1, 256>>>(out);
}

// round 13
// speedup vs baseline: 1.0468x; 1.0468x over previous
#include <cuda_runtime.h>
#include <cuda_bf16.h>
#include <math.h>
#include <stdint.h>

#define G1 4.0f
#define EPSL 1e-10f

// ---------------- scratch (device globals) ----------------------------------
__device__ float    g_sT[40u*75u*2048u];      // [b][t][r]: s scores
__device__ float    g_rsmax[40u*5u*2048u];    // [b][seg][r] row max
__device__ float    g_rsinv[40u*5u*2048u];    // [b][seg][r] 1/sumexp
__device__ float    g_cinv_nt[40*75];
__device__ float    g_sd[40*8*75];
__device__ uint32_t g_aH[40u*75u*1024u];      // alpha numerators, bf16-hi pairs
__device__ uint32_t g_aL[40u*75u*1024u];      // alpha numerators, bf16-lo pairs
__device__ uint32_t g_eh[8*75*128];           // text bf16-hi pairs
__device__ uint32_t g_el2[8*75*128];          // text bf16-lo pairs
__device__ float    g_vtp[8u*40u*75u*256u];   // split-K partials of v_tidal
__device__ float    g_vns[40*8*256];
__device__ float    g_el[40*75];
__device__ float    g_logit2[40*8*5];
__device__ float    g_regval[40];

// ---------------- helpers ----------------------------------------------------
__device__ __forceinline__ uint32_t s2u(const void* p) {
    uint32_t a;
    asm("{ .reg .u64 t; cvta.to.shared.u64 t, %1; cvt.u32.u64 %0, t; }" : "=r"(a) : "l"(p));
    return a;
}
__device__ __forceinline__ void cp16(uint32_t dst, const void* src) {
    asm volatile("cp.async.cg.shared.global [%0], [%1], 16;" :: "r"(dst), "l"(src));
}
__device__ __forceinline__ void cp_commit() { asm volatile("cp.async.commit_group;" ::: "memory"); }
__device__ __forceinline__ void cp_wait0()  { asm volatile("cp.async.wait_group 0;" ::: "memory"); }

__device__ __forceinline__ void ldm_x4(uint32_t& r0, uint32_t& r1, uint32_t& r2,
                                       uint32_t& r3, uint32_t addr) {
    asm volatile("ldmatrix.sync.aligned.m8n8.x4.shared.b16 {%0,%1,%2,%3}, [%4];"
                 : "=r"(r0), "=r"(r1), "=r"(r2), "=r"(r3) : "r"(addr));
}
__device__ __forceinline__ void ldm_x4_t(uint32_t& r0, uint32_t& r1, uint32_t& r2,
                                         uint32_t& r3, uint32_t addr) {
    asm volatile("ldmatrix.sync.aligned.m8n8.x4.trans.shared.b16 {%0,%1,%2,%3}, [%4];"
                 : "=r"(r0), "=r"(r1), "=r"(r2), "=r"(r3) : "r"(addr));
}
__device__ __forceinline__ void mma_bf16(float* c, uint32_t a0, uint32_t a1,
                                         uint32_t a2, uint32_t a3,
                                         uint32_t b0, uint32_t b1) {
    asm volatile(
        "mma.sync.aligned.m16n8k16.row.col.f32.bf16.bf16.f32 "
        "{%0,%1,%2,%3}, {%4,%5,%6,%7}, {%8,%9}, {%0,%1,%2,%3};"
        : "+f"(c[0]), "+f"(c[1]), "+f"(c[2]), "+f"(c[3])
        : "r"(a0), "r"(a1), "r"(a2), "r"(a3), "r"(b0), "r"(b1));
}
// fast split: x,y -> packed bf16 hi + packed bf16 lo residual
__device__ __forceinline__ void bsplit2(float x, float y, uint32_t& hi, uint32_t& lo) {
    uint32_t h;
    asm("cvt.rn.bf16x2.f32 %0, %1, %2;" : "=r"(h) : "f"(y), "f"(x));
    float hx = __uint_as_float(h << 16);
    float hy = __uint_as_float(h & 0xFFFF0000u);
    float lx = x - hx, ly = y - hy;
    asm("cvt.rn.bf16x2.f32 %0, %1, %2;" : "=r"(lo) : "f"(ly), "f"(lx));
    hi = h;
}

// phase1 per-stage 30208 B: AH[32 k][272 B] @0 | AL @8704 | BH[80][20w] @17408 | BL @23808
#define P1_ST  30208
#define P1_SZ  60416
// vtidal: per-stage 33280 B: AH[80][20] @0 | AL @6400 | BH[128][20] @12800 | BL @23040
#define P3_ST  33280
#define P3_SZ  66560

// ============ PHASE 0: convert text to bf16 hi/lo pairs =====================
__global__ void __launch_bounds__(256) k_prep(const float* __restrict__ text) {
    int i = blockIdx.x * 256 + threadIdx.x;   // 76800 pairs
    float2 v = *(const float2*)(text + 2 * i);
    uint32_t h, l;
    bsplit2(v.x, v.y, h, l);
    g_eh[i] = h; g_el2[i] = l;
}

// ============ PHASE 1: pipelined mma gemm_s (640 blks) ======================
__global__ void __launch_bounds__(256) k_phase1(const float* __restrict__ image,
                                                const float* __restrict__ text) {
    extern __shared__ __align__(16) char dsm[];
    const int bx = blockIdx.x;
    const int tid = threadIdx.x;
    const int wid = tid >> 5, lane = tid & 31;

    const int b  = bx >> 4;
    const int rb = bx & 15;
    const int r0 = rb * 128;
    const int m  = rb >> 1, p0 = (rb & 1) * 128;
    const float* srcA = image + (size_t)(b * 8 + m) * 65536;
    const uint32_t* eH = g_eh  + (size_t)(b / 5) * 9600;
    const uint32_t* eL = g_el2 + (size_t)(b / 5) * 9600;
    const uint32_t sbase = s2u(dsm);
    const int gid = lane >> 2, tig = lane & 3;

    // zero B pad rows 75..79 in both stages
    for (int i = tid; i < 100; i += 256) {
        #pragma unroll
        for (int s = 0; s < 2; s++) {
            *(uint32_t*)(dsm + s * P1_ST + 17408 + (1500 + i) * 4) = 0;
            *(uint32_t*)(dsm + s * P1_ST + 23808 + (1500 + i) * 4) = 0;
        }
    }

    float4 iv[4];
    auto load_a = [&](int c) {
        const int kb = c * 32;
        #pragma unroll
        for (int it = 0; it < 4; it++) {
            int lin = tid + it * 256;
            int k = lin >> 5, f4 = (lin & 31) * 4;
            iv[it] = *(const float4*)(srcA + (size_t)(kb + k) * 256 + p0 + f4);
        }
    };
    // convert in regs, store bf16 hi/lo to [k][p] tile (272 B rows)
    auto store_a = [&](int s) {
        char* AH = dsm + s * P1_ST;
        char* AL = AH + 8704;
        #pragma unroll
        for (int it = 0; it < 4; it++) {
            int lin = tid + it * 256;
            int k = lin >> 5, p4 = (lin & 31) * 4;
            uint32_t h0, l0, h1, l1;
            bsplit2(iv[it].x, iv[it].y, h0, l0);
            bsplit2(iv[it].z, iv[it].w, h1, l1);
            int off = k * 272 + p4 * 2;
            *(uint2*)(AH + off) = make_uint2(h0, h1);
            *(uint2*)(AL + off) = make_uint2(l0, l1);
        }
    };
    auto stage_b = [&](int c, int s) {
        const int kw = c * 16;
        #pragma unroll
        for (int i = 0; i < 3; i++) {
            int idx = tid + i * 256;
            if (idx < 600) {
                int half = (idx >= 300) ? 1 : 0;
                int j = idx - half * 300;
                int t = j >> 2, c4 = (j & 3) * 4;
                const uint32_t* src = (half ? eL : eH) + t * 128 + kw + c4;
                cp16(sbase + s * P1_ST + 17408 + half * 6400 + (t * 20 + c4) * 4, src);
            }
        }
        cp_commit();
    };

    float acc[10][4];
    #pragma unroll
    for (int nt = 0; nt < 10; nt++)
        #pragma unroll
        for (int q = 0; q < 4; q++) acc[nt][q] = 0.f;

    // ldmatrix.trans A base: lanes -> k-rows, matrices -> (m-half, k-half)
    const uint32_t aoffT = (uint32_t)(((lane & 7) + ((lane >> 4) & 1) * 8) * 272
                                      + ((lane >> 3) & 1) * 16 + wid * 32);
    const uint32_t boff0 = (uint32_t)((((lane >> 4) & 1) * 8 + (lane & 7)) * 80
                                      + ((lane >> 3) & 1) * 16);

    // prologue: chunk 0
    load_a(0);
    stage_b(0, 0);
    store_a(0);
    cp_wait0();
    __syncthreads();

    for (int c = 0; c < 8; c++) {
        const int s = c & 1;
        if (c < 7) { load_a(c + 1); stage_b(c + 1, s ^ 1); }
        // ---- mma on stage s ------------------------------------------
        {
            const uint32_t pAH = sbase + s * P1_ST;
            const uint32_t pAL = pAH + 8704;
            const uint32_t pBH = pAH + 17408;
            const uint32_t pBL = pAH + 23808;
            #pragma unroll
            for (int ks = 0; ks < 2; ks++) {
                uint32_t ah0, ah1, ah2, ah3, al0, al1, al2, al3;
                ldm_x4_t(ah0, ah1, ah2, ah3, pAH + aoffT + ks * 4352);
                ldm_x4_t(al0, al1, al2, al3, pAL + aoffT + ks * 4352);
                #pragma unroll
                for (int j = 0; j < 5; j++) {
                    uint32_t bh0, bh1, bh2, bh3, bl0, bl1, bl2, bl3;
                    uint32_t bo = boff0 + (uint32_t)(j * 16 * 80 + ks * 32);
                    ldm_x4(bh0, bh1, bh2, bh3, pBH + bo);
                    ldm_x4(bl0, bl1, bl2, bl3, pBL + bo);
                    mma_bf16(acc[2 * j],     ah0, ah1, ah2, ah3, bh0, bh1);
                    mma_bf16(acc[2 * j + 1], ah0, ah1, ah2, ah3, bh2, bh3);
                    mma_bf16(acc[2 * j],     ah0, ah1, ah2, ah3, bl0, bl1);
                    mma_bf16(acc[2 * j + 1], ah0, ah1, ah2, ah3, bl2, bl3);
                    mma_bf16(acc[2 * j],     al0, al1, al2, al3, bh0, bh1);
                    mma_bf16(acc[2 * j + 1], al0, al1, al2, al3, bh2, bh3);
                }
            }
        }
        if (c < 7) { store_a(s ^ 1); cp_wait0(); }
        __syncthreads();
    }
    // ---- epilogue: stage C to sc[t][132 r] --------------------------
    float* sc = (float*)dsm;
    const int rA = wid * 16 + gid;
    #pragma unroll
    for (int nt = 0; nt < 10; nt++) {
        int t0 = nt * 8 + tig * 2;
        sc[t0 * 132 + rA]           = acc[nt][0];
        sc[(t0 + 1) * 132 + rA]     = acc[nt][1];
        sc[t0 * 132 + rA + 8]       = acc[nt][2];
        sc[(t0 + 1) * 132 + rA + 8] = acc[nt][3];
    }
    __syncthreads();
    if (tid < 128) {
        const int r = tid;
        #pragma unroll
        for (int seg = 0; seg < 5; seg++) {
            float mx = -3.4e38f;
            #pragma unroll
            for (int l = 0; l < 15; l++)
                mx = fmaxf(mx, sc[(seg * 15 + l) * 132 + r]);
            float se = 0.f;
            #pragma unroll
            for (int l = 0; l < 15; l++)
                se += __expf(sc[(seg * 15 + l) * 132 + r] - mx);
            size_t off = ((size_t)b * 5 + seg) * 2048 + r0 + r;
            g_rsmax[off] = mx;
            g_rsinv[off] = 1.0f / se;
        }
    }
    for (int i = tid; i < 9600; i += 256) {
        int t = i >> 7, r = i & 127;
        g_sT[((size_t)b * 75 + t) * 2048 + r0 + r] = sc[t * 132 + r];
    }
}

// ============ PHASE 2: vns (320, dispatched FIRST) + colstats (3000) =========
__global__ void __launch_bounds__(256) k_colstats(const float* __restrict__ image) {
    const int bx = blockIdx.x;
    const int tid = threadIdx.x, lane = tid & 31, w = tid >> 5;
    __shared__ float sred[256];

    if (bx < 320) {
        // -------- vns from image (runs first, overlaps exp-bound colstats) ---
        const int bm = bx;
        const float* src = image + (size_t)bm * 65536;
        float* invn = sred;
        float s0 = 0.f, s1 = 0.f, s2 = 0.f, s3 = 0.f;
        for (int d = 0; d < 256; d += 4) {
            float x0 = src[(size_t)(d + 0) * 256 + tid];
            float x1 = src[(size_t)(d + 1) * 256 + tid];
            float x2 = src[(size_t)(d + 2) * 256 + tid];
            float x3 = src[(size_t)(d + 3) * 256 + tid];
            s0 = fmaf(x0, x0, s0); s1 = fmaf(x1, x1, s1);
            s2 = fmaf(x2, x2, s2); s3 = fmaf(x3, x3, s3);
        }
        invn[tid] = 1.0f / fmaxf(sqrtf((s0 + s1) + (s2 + s3)), 1e-12f);
        __syncthreads();
        for (int j = 0; j < 32; j++) {
            int d = w * 32 + j;
            const float* row = src + (size_t)d * 256;
            float a = 0.f;
            #pragma unroll
            for (int q = 0; q < 8; q++) {
                int p = lane + 32 * q;
                a = fmaf(row[p], invn[p], a);
            }
            #pragma unroll
            for (int o = 16; o > 0; o >>= 1) a += __shfl_xor_sync(0xffffffffu, a, o);
            if (lane == 0) g_vns[(size_t)bm * 256 + d] = a;
        }
        return;
    }

    const int idx = bx - 320;
    const int b = idx / 75, t = idx % 75, seg = t / 15;
    const float* col = g_sT + ((size_t)b * 75 + t) * 2048;

    float vals[8];
    *(float4*)vals       = *(const float4*)(col + tid * 8);
    *(float4*)(vals + 4) = *(const float4*)(col + tid * 8 + 4);

    float mx = vals[0];
    #pragma unroll
    for (int k = 1; k < 8; k++) mx = fmaxf(mx, vals[k]);
    #pragma unroll
    for (int o = 16; o > 0; o >>= 1) mx = fmaxf(mx, __shfl_xor_sync(0xffffffffu, mx, o));
    if (lane == 0) sred[w] = mx;
    __syncthreads();
    float cmax = sred[0];
    #pragma unroll
    for (int q = 1; q < 8; q++) cmax = fmaxf(cmax, sred[q]);

    // SoA rowstats: vectorized loads
    float mxv[8], inv[8];
    {
        const size_t off = ((size_t)b * 5 + seg) * 2048 + tid * 8;
        *(float4*)mxv       = *(const float4*)(g_rsmax + off);
        *(float4*)(mxv + 4) = *(const float4*)(g_rsmax + off + 4);
        *(float4*)inv       = *(const float4*)(g_rsinv + off);
        *(float4*)(inv + 4) = *(const float4*)(g_rsinv + off + 4);
    }

    float e1[8], al[8];
    float sraw = 0.f, snt = 0.f;
    #pragma unroll
    for (int k = 0; k < 8; k++) {
        e1[k] = __expf(vals[k] - cmax);
        sraw += e1[k];
        al[k] = __expf(G1 * __expf(vals[k] - mxv[k]) * inv[k]);
        snt += al[k];
    }
    {
        uint32_t* aH = g_aH + (size_t)b * 76800 + t * 1024 + tid * 4;
        uint32_t* aL = g_aL + (size_t)b * 76800 + t * 1024 + tid * 4;
        #pragma unroll
        for (int j = 0; j < 4; j++) {
            uint32_t h, l;
            bsplit2(al[2 * j], al[2 * j + 1], h, l);
            aH[j] = h; aL[j] = l;
        }
    }
    float sr = sraw, sn = snt;
    #pragma unroll
    for (int o = 16; o > 0; o >>= 1) {
        sr += __shfl_xor_sync(0xffffffffu, sr, o);
        sn += __shfl_xor_sync(0xffffffffu, sn, o);
    }
    if (lane == 0) { sred[8 + w] = sr; sred[16 + w] = sn; }
    __syncthreads();
    float tot = 0.f;
    #pragma unroll
    for (int q = 0; q < 8; q++) tot += sred[8 + q];
    const float cinv = 1.0f / tot;
    if (tid == 0) {
        float s = 0.f;
        #pragma unroll
        for (int q = 0; q < 8; q++) s += sred[16 + q];
        g_cinv_nt[b * 75 + t] = 1.0f / s;
    }
    float e2 = 0.f;
    #pragma unroll
    for (int k = 0; k < 8; k++) e2 += __expf(e1[k] * cinv);
    #pragma unroll
    for (int o = 16; o > 0; o >>= 1) e2 += __shfl_xor_sync(0xffffffffu, e2, o);
    if (lane == 0) g_sd[((size_t)b * 8 + w) * 75 + t] = e2;
}

// ============ PHASE 3: mma v_tidal (640) + logit2 (320) + reg (40) ===========
__global__ void __launch_bounds__(256) k_vtidal(const float* __restrict__ image,
                                                const float* __restrict__ text) {
    extern __shared__ __align__(16) char dsm[];
    __shared__ float scv[80];
    const int bx = blockIdx.x;
    const int tid = threadIdx.x;
    const int wid = tid >> 5, lane = tid & 31;

    if (bx >= 640) {
        float* pool = (float*)dsm;
        if (bx < 960) {
            // ---- logit2 (overlaps tensor-bound vtidal) ----------------------
            const int idx = bx - 640;
            const int b = idx >> 3, m = idx & 7, blk = b / 5;
            float* shsd = pool;
            float* wred = pool + 16;
            const float vv = g_vns[((size_t)b * 8 + m) * 256 + tid];
            for (int sb = 0; sb < 5; sb++) {
                if (tid < 15) shsd[tid] = g_sd[((size_t)b * 8 + m) * 75 + sb * 15 + tid];
                __syncthreads();
                float segsum = 0.f;
                #pragma unroll
                for (int l = 0; l < 15; l++) segsum += shsd[l];
                float em = 0.f;
                #pragma unroll
                for (int l = 0; l < 15; l++)
                    em = fmaf(shsd[l], text[((size_t)blk * 75 + sb * 15 + l) * 256 + tid], em);
                em /= segsum;
                float p = em * em, q = em * vv;
                #pragma unroll
                for (int o = 16; o > 0; o >>= 1) {
                    p += __shfl_xor_sync(0xffffffffu, p, o);
                    q += __shfl_xor_sync(0xffffffffu, q, o);
                }
                if (lane == 0) { wred[wid] = p; wred[8 + wid] = q; }
                __syncthreads();
                if (tid == 0) {
                    float s1 = 0.f, s2 = 0.f;
                    #pragma unroll
                    for (int j = 0; j < 8; j++) { s1 += wred[j]; s2 += wred[8 + j]; }
                    g_logit2[((size_t)b * 8 + m) * 5 + sb] =
                        s2 / (fmaxf(sqrtf(s1), 1e-12f) * 256.0f);
                }
                __syncthreads();
            }
        } else {
            // ---- beta decorrelation regularizer -----------------------------
            const int b = bx - 960;
            float* ssd   = pool;
            float* sseg  = pool + 600;
            float* sbeta = pool + 640;
            float* red   = pool + 1240;
            for (int i = tid; i < 600; i += 256) ssd[i] = g_sd[(size_t)b * 600 + i];
            __syncthreads();
            if (tid < 40) {
                int m = tid / 5, sb2 = tid % 5;
                float s = 0.f;
                for (int l = 0; l < 15; l++) s += ssd[m * 75 + sb2 * 15 + l];
                sseg[tid] = s;
            }
            __syncthreads();
            for (int i = tid; i < 600; i += 256) {
                int m = i / 75, t = i % 75;
                sbeta[i] = ssd[i] / sseg[m * 5 + t / 15];
            }
            __syncthreads();
            float p = 0.f;
            if (tid < 64) {
                int m = tid >> 3, n = tid & 7;
                if (m != n) {
                    float a = 0.f;
                    for (int t = 0; t < 75; t++)
                        a = fmaf(sbeta[m * 75 + t], sbeta[n * 75 + t], a);
                    p = a * a;
                }
            }
            red[tid] = p; __syncthreads();
            for (int o = 128; o > 0; o >>= 1) {
                if (tid < o) red[tid] += red[tid + o];
                __syncthreads();
            }
            if (tid == 0) g_regval[b] = sqrtf(red[0]);
        }
        return;
    }

    const int b  = bx >> 4;
    const int kz = (bx >> 1) & 7;
    const int nh = bx & 1;
    const int gid = lane >> 2, tig = lane & 3;
    const uint32_t sbase = s2u(dsm);
    const uint32_t* aHg = g_aH + (size_t)b * 76800;
    const uint32_t* aLg = g_aL + (size_t)b * 76800;
    const float* srcB = image + (size_t)(b * 8 + kz) * 65536 + (size_t)(nh * 128) * 256;

    if (tid < 75) scv[tid] = g_cinv_nt[b * 75 + tid];
    // zero A pad rows 75..79 in both stages
    for (int i = tid; i < 100; i += 256) {
        #pragma unroll
        for (int s = 0; s < 2; s++) {
            *(uint32_t*)(dsm + s * P3_ST +        (1500 + i) * 4) = 0;
            *(uint32_t*)(dsm + s * P3_ST + 6400 + (1500 + i) * 4) = 0;
        }
    }

    auto stage_a = [&](int c, int s) {
        const int rgw = (kz * 256 + c * 32) >> 1;
        #pragma unroll
        for (int i = 0; i < 3; i++) {
            int idx = tid + i * 256;
            if (idx < 600) {
                int half = (idx >= 300) ? 1 : 0;
                int j = idx - half * 300;
                int t = j >> 2, c4 = (j & 3) * 4;
                const uint32_t* src = (half ? aLg : aHg) + t * 1024 + rgw + c4;
                cp16(sbase + s * P3_ST + half * 6400 + (t * 20 + c4) * 4, src);
            }
        }
        cp_commit();
    };

    float4 vb[4];
    auto load_b = [&](int c) {
        const int p0 = c * 32;
        #pragma unroll
        for (int it = 0; it < 4; it++) {
            int idx = tid + it * 256;
            int d = idx >> 3, c4 = (idx & 7) * 4;
            vb[it] = *(const float4*)(srcB + (size_t)d * 256 + p0 + c4);
        }
    };
    auto store_b = [&](int s) {
        uint32_t* BH = (uint32_t*)(dsm + s * P3_ST + 12800);
        uint32_t* BL = (uint32_t*)(dsm + s * P3_ST + 23040);
        #pragma unroll
        for (int it = 0; it < 4; it++) {
            int idx = tid + it * 256;
            int d = idx >> 3, c4 = (idx & 7) * 4;
            uint32_t h0, l0, h1, l1;
            bsplit2(vb[it].x, vb[it].y, h0, l0);
            bsplit2(vb[it].z, vb[it].w, h1, l1);
            int w0 = d * 20 + (c4 >> 1);
            BH[w0] = h0; BH[w0 + 1] = h1;
            BL[w0] = l0; BL[w0 + 1] = l1;
        }
    };

    float acc[5][2][4];
    #pragma unroll
    for (int mt = 0; mt < 5; mt++)
        #pragma unroll
        for (int nt = 0; nt < 2; nt++)
            #pragma unroll
            for (int q = 0; q < 4; q++) acc[mt][nt][q] = 0.f;

    // prologue: chunk 0
    stage_a(0, 0);
    load_b(0);
    store_b(0);
    cp_wait0();
    __syncthreads();

    const int n0 = wid * 16;
    const uint32_t aoffb = (uint32_t)((lane & 15) * 80 + (lane >> 4) * 16);
    const uint32_t boff0 = (uint32_t)((n0 + ((lane >> 4) & 1) * 8 + (lane & 7)) * 80
                                      + ((lane >> 3) & 1) * 16);

    for (int c = 0; c < 8; c++) {
        const int s = c & 1;
        if (c < 7) { stage_a(c + 1, s ^ 1); load_b(c + 1); }
        // ---- mma on stage s (interleaved accumulators) -------------------
        {
            const uint32_t pAH = sbase + s * P3_ST;
            const uint32_t pAL = pAH + 6400;
            const uint32_t pBH = pAH + 12800;
            const uint32_t pBL = pAH + 23040;
            #pragma unroll
            for (int ks = 0; ks < 2; ks++) {
                uint32_t bh0, bh1, bh2, bh3, bl0, bl1, bl2, bl3;
                ldm_x4(bh0, bh1, bh2, bh3, pBH + boff0 + ks * 32);
                ldm_x4(bl0, bl1, bl2, bl3, pBL + boff0 + ks * 32);
                #pragma unroll
                for (int mt = 0; mt < 5; mt++) {
                    uint32_t ah0, ah1, ah2, ah3, al0, al1, al2, al3;
                    uint32_t ao = aoffb + (uint32_t)(mt * 16 * 80 + ks * 32);
                    ldm_x4(ah0, ah1, ah2, ah3, pAH + ao);
                    ldm_x4(al0, al1, al2, al3, pAL + ao);
                    mma_bf16(acc[mt][0], ah0, ah1, ah2, ah3, bh0, bh1);
                    mma_bf16(acc[mt][1], ah0, ah1, ah2, ah3, bh2, bh3);
                    mma_bf16(acc[mt][0], ah0, ah1, ah2, ah3, bl0, bl1);
                    mma_bf16(acc[mt][1], ah0, ah1, ah2, ah3, bl2, bl3);
                    mma_bf16(acc[mt][0], al0, al1, al2, al3, bh0, bh1);
                    mma_bf16(acc[mt][1], al0, al1, al2, al3, bh2, bh3);
                }
            }
        }
        if (c < 7) { store_b(s ^ 1); cp_wait0(); }
        __syncthreads();
    }
    // ---- epilogue: scale by cinv[t], write split-K partials -----------------
    float* outp = g_vtp + (size_t)kz * 40 * 75 * 256 + (size_t)b * 75 * 256 + nh * 128;
    #pragma unroll
    for (int mt = 0; mt < 5; mt++) {
        int t = mt * 16 + gid;
        #pragma unroll
        for (int nt = 0; nt < 2; nt++) {
            int d = n0 + nt * 8 + tig * 2;
            if (t < 75) {
                float ci = scv[t];
                float2 v0 = {acc[mt][nt][0] * ci, acc[mt][nt][1] * ci};
                *(float2*)(outp + (size_t)t * 256 + d) = v0;
            }
            if (t + 8 < 75) {
                float ci = scv[t + 8];
                float2 v1 = {acc[mt][nt][2] * ci, acc[mt][nt][3] * ci};
                *(float2*)(outp + (size_t)(t + 8) * 256 + d) = v1;
            }
        }
    }
}

// ============ PHASE 4: score1 only (375 blocks) =============================
__global__ void __launch_bounds__(256) k_tail(const float* __restrict__ text) {
    const int tid = threadIdx.x;
    const int lane = tid & 31, w = tid >> 5;
    const int gt = blockIdx.x * 8 + w;
    if (gt < 3000) {
        const int b = gt / 75, t = gt % 75, blk = b / 5;
        const size_t SL = (size_t)40 * 75 * 256;
        const size_t voff = ((size_t)b * 75 + t) * 256;
        const float* e = text + ((size_t)blk * 75 + t) * 256;
        float dot = 0.f, nv = 0.f, ne = 0.f;
        #pragma unroll
        for (int j = 0; j < 8; j++) {
            int d = lane + 32 * j;
            float a = 0.f;
            #pragma unroll
            for (int s8 = 0; s8 < 8; s8++) a += g_vtp[s8 * SL + voff + d];
            float cc = e[d];
            dot = fmaf(a, cc, dot); nv = fmaf(a, a, nv); ne = fmaf(cc, cc, ne);
        }
        #pragma unroll
        for (int o = 16; o > 0; o >>= 1) {
            dot += __shfl_xor_sync(0xffffffffu, dot, o);
            nv  += __shfl_xor_sync(0xffffffffu, nv,  o);
            ne  += __shfl_xor_sync(0xffffffffu, ne,  o);
        }
        if (lane == 0)
            g_el[b * 75 + t] = __expf(dot / (fmaxf(sqrtf(nv), 1e-12f) * fmaxf(sqrtf(ne), 1e-12f)));
    }
}

// ============ PHASE 5: final scalar =========================================
__global__ void k_final(float* __restrict__ out) {
    const int tid = threadIdx.x;
    __shared__ float lsm[200];
    __shared__ float bscore[8];
    if (tid < 200) {
        int blk = tid / 25, rem = tid % 25, i = rem / 5, sb = rem % 5;
        int gi = blk * 5 + i;
        float s2 = 0.f;
        #pragma unroll
        for (int m = 0; m < 8; m++) s2 += __expf(g_logit2[((size_t)gi * 8 + m) * 5 + sb]);
        float s1 = 0.f;
        #pragma unroll
        for (int l = 0; l < 15; l++) s1 += g_el[gi * 75 + sb * 15 + l];
        float l1 = __logf(__powf(s1, 0.2f) + EPSL);
        float l2 = __logf(__powf(s2, 0.2f) + EPSL);
        lsm[tid] = 10.0f * (l1 + l2);
    }
    __syncthreads();
    if (tid < 8) {
        const float* L = lsm + tid * 25;
        float rows[5] = {0, 0, 0, 0, 0}, cols[5] = {0, 0, 0, 0, 0};
        for (int i = 0; i < 5; i++)
            for (int sb = 0; sb < 5; sb++) {
                rows[i] += L[i * 5 + sb];
                cols[sb] += L[i * 5 + sb];
            }
        float acc = 0.f;
        for (int i = 0; i < 5; i++) {
            float dg = L[i * 5 + i];
            acc += -__logf(dg / rows[i] + EPSL) - __logf(dg / cols[i] + EPSL);
        }
        float reg = 0.f;
        for (int i = 0; i < 5; i++) reg += g_regval[tid * 5 + i];
        bscore[tid] = acc / 5.0f + reg / 5.0f;
    }
    __syncthreads();
    if (tid == 0) {
        float tot = 0.f;
        for (int k = 0; k < 8; k++) tot += bscore[k];
        out[0] = tot / 9.0f;
    }
}

// ---------------- launch -----------------------------------------------------
extern "C" void kernel_launch(void* const* d_in, const int* in_sizes, int n_in,
                              void* d_out, int out_size) {
    (void)in_sizes; (void)n_in; (void)out_size;
    const float* image = (const float*)d_in[0];
    const float* text  = (const float*)d_in[1];
    float* out = (float*)d_out;

    cudaFuncSetAttribute(k_phase1, cudaFuncAttributeMaxDynamicSharedMemorySize, P1_SZ);
    cudaFuncSetAttribute(k_vtidal, cudaFuncAttributeMaxDynamicSharedMemorySize, P3_SZ);

    k_prep<<<300, 256>>>(text);
    k_phase1<<<640, 256, P1_SZ>>>(image, text);
    k_colstats<<<3320, 256>>>(image);
    k_vtidal<<<1000, 256, P3_SZ>>>(image, text);
    k_tail<<<375, 256>>>(text);
    k_final<<<1, 256>>>(out);
}

// round 14
// speedup vs baseline: 1.1265x; 1.0761x over previous
#include <cuda_runtime.h>
#include <cuda_bf16.h>
#include <math.h>
#include <stdint.h>

#define G1 4.0f
#define EPSL 1e-10f

// ---------------- scratch (device globals) ----------------------------------
__device__ float    g_sT[40u*75u*2048u];      // [b][t][r]: s scores
__device__ float    g_rsmax[40u*5u*2048u];    // [b][seg][r] row max
__device__ float    g_rsinv[40u*5u*2048u];    // [b][seg][r] 1/sumexp
__device__ float    g_cinv_nt[40*75];
__device__ float    g_sd[40*8*75];
__device__ uint32_t g_aH[40u*75u*1024u];      // alpha numerators, bf16-hi pairs
__device__ uint32_t g_aL[40u*75u*1024u];      // alpha numerators, bf16-lo pairs
__device__ uint32_t g_eh[8*75*128];           // text bf16-hi pairs
__device__ uint32_t g_el2[8*75*128];          // text bf16-lo pairs
__device__ float    g_vtp[8u*40u*75u*256u];   // split-K partials of v_tidal
__device__ float    g_vns[40*8*256];
__device__ float    g_el[40*75];
__device__ float    g_logit2[40*8*5];
__device__ float    g_regval[40];

// ---------------- helpers ----------------------------------------------------
__device__ __forceinline__ uint32_t s2u(const void* p) {
    uint32_t a;
    asm("{ .reg .u64 t; cvta.to.shared.u64 t, %1; cvt.u32.u64 %0, t; }" : "=r"(a) : "l"(p));
    return a;
}
__device__ __forceinline__ void cp16(uint32_t dst, const void* src) {
    asm volatile("cp.async.cg.shared.global [%0], [%1], 16;" :: "r"(dst), "l"(src));
}
__device__ __forceinline__ void cp_commit() { asm volatile("cp.async.commit_group;" ::: "memory"); }
__device__ __forceinline__ void cp_wait0()  { asm volatile("cp.async.wait_group 0;" ::: "memory"); }

__device__ __forceinline__ void ldm_x4(uint32_t& r0, uint32_t& r1, uint32_t& r2,
                                       uint32_t& r3, uint32_t addr) {
    asm volatile("ldmatrix.sync.aligned.m8n8.x4.shared.b16 {%0,%1,%2,%3}, [%4];"
                 : "=r"(r0), "=r"(r1), "=r"(r2), "=r"(r3) : "r"(addr));
}
__device__ __forceinline__ void ldm_x4_t(uint32_t& r0, uint32_t& r1, uint32_t& r2,
                                         uint32_t& r3, uint32_t addr) {
    asm volatile("ldmatrix.sync.aligned.m8n8.x4.trans.shared.b16 {%0,%1,%2,%3}, [%4];"
                 : "=r"(r0), "=r"(r1), "=r"(r2), "=r"(r3) : "r"(addr));
}
__device__ __forceinline__ void mma_bf16(float* c, uint32_t a0, uint32_t a1,
                                         uint32_t a2, uint32_t a3,
                                         uint32_t b0, uint32_t b1) {
    asm volatile(
        "mma.sync.aligned.m16n8k16.row.col.f32.bf16.bf16.f32 "
        "{%0,%1,%2,%3}, {%4,%5,%6,%7}, {%8,%9}, {%0,%1,%2,%3};"
        : "+f"(c[0]), "+f"(c[1]), "+f"(c[2]), "+f"(c[3])
        : "r"(a0), "r"(a1), "r"(a2), "r"(a3), "r"(b0), "r"(b1));
}
// fast split: x,y -> packed bf16 hi + packed bf16 lo residual
__device__ __forceinline__ void bsplit2(float x, float y, uint32_t& hi, uint32_t& lo) {
    uint32_t h;
    asm("cvt.rn.bf16x2.f32 %0, %1, %2;" : "=r"(h) : "f"(y), "f"(x));
    float hx = __uint_as_float(h << 16);
    float hy = __uint_as_float(h & 0xFFFF0000u);
    float lx = x - hx, ly = y - hy;
    asm("cvt.rn.bf16x2.f32 %0, %1, %2;" : "=r"(lo) : "f"(ly), "f"(lx));
    hi = h;
}

// phase1 per-stage 30208 B: AH[32 k][272 B] @0 | AL @8704 | BH[80][20w] @17408 | BL @23808
#define P1_ST  30208
#define P1_SZ  60416
// vtidal: per-stage 33280 B: AH[80][20] @0 | AL @6400 | BH[128][20] @12800 | BL @23040
#define P3_ST  33280
#define P3_SZ  66560

// ============ PHASE 0: convert text to bf16 hi/lo pairs =====================
__global__ void __launch_bounds__(256) k_prep(const float* __restrict__ text) {
    int i = blockIdx.x * 256 + threadIdx.x;   // 76800 pairs
    float2 v = *(const float2*)(text + 2 * i);
    uint32_t h, l;
    bsplit2(v.x, v.y, h, l);
    g_eh[i] = h; g_el2[i] = l;
}

// ============ PHASE 1: vns (320, first) + pipelined mma gemm_s (640) ========
__global__ void __launch_bounds__(256) k_phase1(const float* __restrict__ image,
                                                const float* __restrict__ text) {
    extern __shared__ __align__(16) char dsm[];
    const int bx = blockIdx.x;
    const int tid = threadIdx.x;
    const int wid = tid >> 5, lane = tid & 31;

    if (bx < 320) {
        // -------- vns (hidden inside the long GEMM kernel) --------------------
        const int bm = bx;
        const float* src = image + (size_t)bm * 65536;
        float* invn = (float*)dsm;
        float s0 = 0.f, s1 = 0.f, s2 = 0.f, s3 = 0.f;
        for (int d = 0; d < 256; d += 4) {
            float x0 = src[(size_t)(d + 0) * 256 + tid];
            float x1 = src[(size_t)(d + 1) * 256 + tid];
            float x2 = src[(size_t)(d + 2) * 256 + tid];
            float x3 = src[(size_t)(d + 3) * 256 + tid];
            s0 = fmaf(x0, x0, s0); s1 = fmaf(x1, x1, s1);
            s2 = fmaf(x2, x2, s2); s3 = fmaf(x3, x3, s3);
        }
        invn[tid] = 1.0f / fmaxf(sqrtf((s0 + s1) + (s2 + s3)), 1e-12f);
        __syncthreads();
        for (int j = 0; j < 32; j++) {
            int d = wid * 32 + j;
            const float* row = src + (size_t)d * 256;
            float a = 0.f;
            #pragma unroll
            for (int q = 0; q < 8; q++) {
                int p = lane + 32 * q;
                a = fmaf(row[p], invn[p], a);
            }
            #pragma unroll
            for (int o = 16; o > 0; o >>= 1) a += __shfl_xor_sync(0xffffffffu, a, o);
            if (lane == 0) g_vns[(size_t)bm * 256 + d] = a;
        }
        return;
    }

    const int bxx = bx - 320;
    const int b  = bxx >> 4;
    const int rb = bxx & 15;
    const int r0 = rb * 128;
    const int m  = rb >> 1, p0 = (rb & 1) * 128;
    const float* srcA = image + (size_t)(b * 8 + m) * 65536;
    const uint32_t* eH = g_eh  + (size_t)(b / 5) * 9600;
    const uint32_t* eL = g_el2 + (size_t)(b / 5) * 9600;
    const uint32_t sbase = s2u(dsm);
    const int gid = lane >> 2, tig = lane & 3;

    // zero B pad rows 75..79 in both stages
    for (int i = tid; i < 100; i += 256) {
        #pragma unroll
        for (int s = 0; s < 2; s++) {
            *(uint32_t*)(dsm + s * P1_ST + 17408 + (1500 + i) * 4) = 0;
            *(uint32_t*)(dsm + s * P1_ST + 23808 + (1500 + i) * 4) = 0;
        }
    }

    float4 iv[4];
    auto load_a = [&](int c) {
        const int kb = c * 32;
        #pragma unroll
        for (int it = 0; it < 4; it++) {
            int lin = tid + it * 256;
            int k = lin >> 5, f4 = (lin & 31) * 4;
            iv[it] = *(const float4*)(srcA + (size_t)(kb + k) * 256 + p0 + f4);
        }
    };
    // convert in regs, store bf16 hi/lo to [k][p] tile (272 B rows)
    auto store_a = [&](int s) {
        char* AH = dsm + s * P1_ST;
        char* AL = AH + 8704;
        #pragma unroll
        for (int it = 0; it < 4; it++) {
            int lin = tid + it * 256;
            int k = lin >> 5, p4 = (lin & 31) * 4;
            uint32_t h0, l0, h1, l1;
            bsplit2(iv[it].x, iv[it].y, h0, l0);
            bsplit2(iv[it].z, iv[it].w, h1, l1);
            int off = k * 272 + p4 * 2;
            *(uint2*)(AH + off) = make_uint2(h0, h1);
            *(uint2*)(AL + off) = make_uint2(l0, l1);
        }
    };
    auto stage_b = [&](int c, int s) {
        const int kw = c * 16;
        #pragma unroll
        for (int i = 0; i < 3; i++) {
            int idx = tid + i * 256;
            if (idx < 600) {
                int half = (idx >= 300) ? 1 : 0;
                int j = idx - half * 300;
                int t = j >> 2, c4 = (j & 3) * 4;
                const uint32_t* src = (half ? eL : eH) + t * 128 + kw + c4;
                cp16(sbase + s * P1_ST + 17408 + half * 6400 + (t * 20 + c4) * 4, src);
            }
        }
        cp_commit();
    };

    float acc[10][4];
    #pragma unroll
    for (int nt = 0; nt < 10; nt++)
        #pragma unroll
        for (int q = 0; q < 4; q++) acc[nt][q] = 0.f;

    // ldmatrix.trans A base: lanes -> k-rows, matrices -> (m-half, k-half)
    const uint32_t aoffT = (uint32_t)(((lane & 7) + ((lane >> 4) & 1) * 8) * 272
                                      + ((lane >> 3) & 1) * 16 + wid * 32);
    const uint32_t boff0 = (uint32_t)((((lane >> 4) & 1) * 8 + (lane & 7)) * 80
                                      + ((lane >> 3) & 1) * 16);

    // prologue: chunk 0
    load_a(0);
    stage_b(0, 0);
    store_a(0);
    cp_wait0();
    __syncthreads();

    for (int c = 0; c < 8; c++) {
        const int s = c & 1;
        if (c < 7) { load_a(c + 1); stage_b(c + 1, s ^ 1); }
        // ---- mma on stage s ------------------------------------------
        {
            const uint32_t pAH = sbase + s * P1_ST;
            const uint32_t pAL = pAH + 8704;
            const uint32_t pBH = pAH + 17408;
            const uint32_t pBL = pAH + 23808;
            #pragma unroll
            for (int ks = 0; ks < 2; ks++) {
                uint32_t ah0, ah1, ah2, ah3, al0, al1, al2, al3;
                ldm_x4_t(ah0, ah1, ah2, ah3, pAH + aoffT + ks * 4352);
                ldm_x4_t(al0, al1, al2, al3, pAL + aoffT + ks * 4352);
                #pragma unroll
                for (int j = 0; j < 5; j++) {
                    uint32_t bh0, bh1, bh2, bh3, bl0, bl1, bl2, bl3;
                    uint32_t bo = boff0 + (uint32_t)(j * 16 * 80 + ks * 32);
                    ldm_x4(bh0, bh1, bh2, bh3, pBH + bo);
                    ldm_x4(bl0, bl1, bl2, bl3, pBL + bo);
                    mma_bf16(acc[2 * j],     ah0, ah1, ah2, ah3, bh0, bh1);
                    mma_bf16(acc[2 * j + 1], ah0, ah1, ah2, ah3, bh2, bh3);
                    mma_bf16(acc[2 * j],     ah0, ah1, ah2, ah3, bl0, bl1);
                    mma_bf16(acc[2 * j + 1], ah0, ah1, ah2, ah3, bl2, bl3);
                    mma_bf16(acc[2 * j],     al0, al1, al2, al3, bh0, bh1);
                    mma_bf16(acc[2 * j + 1], al0, al1, al2, al3, bh2, bh3);
                }
            }
        }
        if (c < 7) { store_a(s ^ 1); cp_wait0(); }
        __syncthreads();
    }
    // ---- epilogue: stage C to sc[t][132 r] --------------------------
    float* sc = (float*)dsm;
    const int rA = wid * 16 + gid;
    #pragma unroll
    for (int nt = 0; nt < 10; nt++) {
        int t0 = nt * 8 + tig * 2;
        sc[t0 * 132 + rA]           = acc[nt][0];
        sc[(t0 + 1) * 132 + rA]     = acc[nt][1];
        sc[t0 * 132 + rA + 8]       = acc[nt][2];
        sc[(t0 + 1) * 132 + rA + 8] = acc[nt][3];
    }
    __syncthreads();
    if (tid < 128) {
        const int r = tid;
        #pragma unroll
        for (int seg = 0; seg < 5; seg++) {
            float mx = -3.4e38f;
            #pragma unroll
            for (int l = 0; l < 15; l++)
                mx = fmaxf(mx, sc[(seg * 15 + l) * 132 + r]);
            float se = 0.f;
            #pragma unroll
            for (int l = 0; l < 15; l++)
                se += __expf(sc[(seg * 15 + l) * 132 + r] - mx);
            size_t off = ((size_t)b * 5 + seg) * 2048 + r0 + r;
            g_rsmax[off] = mx;
            g_rsinv[off] = 1.0f / se;
        }
    }
    for (int i = tid; i < 9600; i += 256) {
        int t = i >> 7, r = i & 127;
        g_sT[((size_t)b * 75 + t) * 2048 + r0 + r] = sc[t * 132 + r];
    }
}

// ============ PHASE 2: colstats (3000, pure) ================================
__global__ void __launch_bounds__(256) k_colstats() {
    const int bx = blockIdx.x;
    const int tid = threadIdx.x, lane = tid & 31, w = tid >> 5;
    __shared__ float sred[24];

    const int b = bx / 75, t = bx % 75, seg = t / 15;
    const float* col = g_sT + ((size_t)b * 75 + t) * 2048;

    float vals[8];
    *(float4*)vals       = *(const float4*)(col + tid * 8);
    *(float4*)(vals + 4) = *(const float4*)(col + tid * 8 + 4);

    float mx = vals[0];
    #pragma unroll
    for (int k = 1; k < 8; k++) mx = fmaxf(mx, vals[k]);
    #pragma unroll
    for (int o = 16; o > 0; o >>= 1) mx = fmaxf(mx, __shfl_xor_sync(0xffffffffu, mx, o));
    if (lane == 0) sred[w] = mx;
    __syncthreads();
    float cmax = sred[0];
    #pragma unroll
    for (int q = 1; q < 8; q++) cmax = fmaxf(cmax, sred[q]);

    // SoA rowstats: vectorized loads
    float mxv[8], inv[8];
    {
        const size_t off = ((size_t)b * 5 + seg) * 2048 + tid * 8;
        *(float4*)mxv       = *(const float4*)(g_rsmax + off);
        *(float4*)(mxv + 4) = *(const float4*)(g_rsmax + off + 4);
        *(float4*)inv       = *(const float4*)(g_rsinv + off);
        *(float4*)(inv + 4) = *(const float4*)(g_rsinv + off + 4);
    }

    float e1[8], al[8];
    float sraw = 0.f, snt = 0.f;
    #pragma unroll
    for (int k = 0; k < 8; k++) {
        e1[k] = __expf(vals[k] - cmax);
        sraw += e1[k];
        al[k] = __expf(G1 * __expf(vals[k] - mxv[k]) * inv[k]);
        snt += al[k];
    }
    {
        uint32_t* aH = g_aH + (size_t)b * 76800 + t * 1024 + tid * 4;
        uint32_t* aL = g_aL + (size_t)b * 76800 + t * 1024 + tid * 4;
        #pragma unroll
        for (int j = 0; j < 4; j++) {
            uint32_t h, l;
            bsplit2(al[2 * j], al[2 * j + 1], h, l);
            aH[j] = h; aL[j] = l;
        }
    }
    float sr = sraw, sn = snt;
    #pragma unroll
    for (int o = 16; o > 0; o >>= 1) {
        sr += __shfl_xor_sync(0xffffffffu, sr, o);
        sn += __shfl_xor_sync(0xffffffffu, sn, o);
    }
    if (lane == 0) { sred[8 + w] = sr; sred[16 + w] = sn; }
    __syncthreads();
    float tot = 0.f;
    #pragma unroll
    for (int q = 0; q < 8; q++) tot += sred[8 + q];
    const float cinv = 1.0f / tot;
    if (tid == 0) {
        float s = 0.f;
        #pragma unroll
        for (int q = 0; q < 8; q++) s += sred[16 + q];
        g_cinv_nt[b * 75 + t] = 1.0f / s;
    }
    float e2 = 0.f;
    #pragma unroll
    for (int k = 0; k < 8; k++) e2 += __expf(e1[k] * cinv);
    #pragma unroll
    for (int o = 16; o > 0; o >>= 1) e2 += __shfl_xor_sync(0xffffffffu, e2, o);
    if (lane == 0) g_sd[((size_t)b * 8 + w) * 75 + t] = e2;
}

// ============ PHASE 3: mma v_tidal (640) + logit2 (320) + reg (40) ===========
__global__ void __launch_bounds__(256) k_vtidal(const float* __restrict__ image,
                                                const float* __restrict__ text) {
    extern __shared__ __align__(16) char dsm[];
    __shared__ float scv[80];
    const int bx = blockIdx.x;
    const int tid = threadIdx.x;
    const int wid = tid >> 5, lane = tid & 31;

    if (bx >= 640) {
        float* pool = (float*)dsm;
        if (bx < 960) {
            // ---- logit2 (overlaps tensor-bound vtidal) ----------------------
            const int idx = bx - 640;
            const int b = idx >> 3, m = idx & 7, blk = b / 5;
            float* shsd = pool;
            float* wred = pool + 16;
            const float vv = g_vns[((size_t)b * 8 + m) * 256 + tid];
            for (int sb = 0; sb < 5; sb++) {
                if (tid < 15) shsd[tid] = g_sd[((size_t)b * 8 + m) * 75 + sb * 15 + tid];
                __syncthreads();
                float segsum = 0.f;
                #pragma unroll
                for (int l = 0; l < 15; l++) segsum += shsd[l];
                float em = 0.f;
                #pragma unroll
                for (int l = 0; l < 15; l++)
                    em = fmaf(shsd[l], text[((size_t)blk * 75 + sb * 15 + l) * 256 + tid], em);
                em /= segsum;
                float p = em * em, q = em * vv;
                #pragma unroll
                for (int o = 16; o > 0; o >>= 1) {
                    p += __shfl_xor_sync(0xffffffffu, p, o);
                    q += __shfl_xor_sync(0xffffffffu, q, o);
                }
                if (lane == 0) { wred[wid] = p; wred[8 + wid] = q; }
                __syncthreads();
                if (tid == 0) {
                    float s1 = 0.f, s2 = 0.f;
                    #pragma unroll
                    for (int j = 0; j < 8; j++) { s1 += wred[j]; s2 += wred[8 + j]; }
                    g_logit2[((size_t)b * 8 + m) * 5 + sb] =
                        s2 / (fmaxf(sqrtf(s1), 1e-12f) * 256.0f);
                }
                __syncthreads();
            }
        } else {
            // ---- beta decorrelation regularizer -----------------------------
            const int b = bx - 960;
            float* ssd   = pool;
            float* sseg  = pool + 600;
            float* sbeta = pool + 640;
            float* red   = pool + 1240;
            for (int i = tid; i < 600; i += 256) ssd[i] = g_sd[(size_t)b * 600 + i];
            __syncthreads();
            if (tid < 40) {
                int m = tid / 5, sb2 = tid % 5;
                float s = 0.f;
                for (int l = 0; l < 15; l++) s += ssd[m * 75 + sb2 * 15 + l];
                sseg[tid] = s;
            }
            __syncthreads();
            for (int i = tid; i < 600; i += 256) {
                int m = i / 75, t = i % 75;
                sbeta[i] = ssd[i] / sseg[m * 5 + t / 15];
            }
            __syncthreads();
            float p = 0.f;
            if (tid < 64) {
                int m = tid >> 3, n = tid & 7;
                if (m != n) {
                    float a = 0.f;
                    for (int t = 0; t < 75; t++)
                        a = fmaf(sbeta[m * 75 + t], sbeta[n * 75 + t], a);
                    p = a * a;
                }
            }
            red[tid] = p; __syncthreads();
            for (int o = 128; o > 0; o >>= 1) {
                if (tid < o) red[tid] += red[tid + o];
                __syncthreads();
            }
            if (tid == 0) g_regval[b] = sqrtf(red[0]);
        }
        return;
    }

    const int b  = bx >> 4;
    const int kz = (bx >> 1) & 7;
    const int nh = bx & 1;
    const int gid = lane >> 2, tig = lane & 3;
    const uint32_t sbase = s2u(dsm);
    const uint32_t* aHg = g_aH + (size_t)b * 76800;
    const uint32_t* aLg = g_aL + (size_t)b * 76800;
    const float* srcB = image + (size_t)(b * 8 + kz) * 65536 + (size_t)(nh * 128) * 256;

    if (tid < 75) scv[tid] = g_cinv_nt[b * 75 + tid];
    // zero A pad rows 75..79 in both stages
    for (int i = tid; i < 100; i += 256) {
        #pragma unroll
        for (int s = 0; s < 2; s++) {
            *(uint32_t*)(dsm + s * P3_ST +        (1500 + i) * 4) = 0;
            *(uint32_t*)(dsm + s * P3_ST + 6400 + (1500 + i) * 4) = 0;
        }
    }

    auto stage_a = [&](int c, int s) {
        const int rgw = (kz * 256 + c * 32) >> 1;
        #pragma unroll
        for (int i = 0; i < 3; i++) {
            int idx = tid + i * 256;
            if (idx < 600) {
                int half = (idx >= 300) ? 1 : 0;
                int j = idx - half * 300;
                int t = j >> 2, c4 = (j & 3) * 4;
                const uint32_t* src = (half ? aLg : aHg) + t * 1024 + rgw + c4;
                cp16(sbase + s * P3_ST + half * 6400 + (t * 20 + c4) * 4, src);
            }
        }
        cp_commit();
    };

    float4 vb[4];
    auto load_b = [&](int c) {
        const int p0 = c * 32;
        #pragma unroll
        for (int it = 0; it < 4; it++) {
            int idx = tid + it * 256;
            int d = idx >> 3, c4 = (idx & 7) * 4;
            vb[it] = *(const float4*)(srcB + (size_t)d * 256 + p0 + c4);
        }
    };
    auto store_b = [&](int s) {
        uint32_t* BH = (uint32_t*)(dsm + s * P3_ST + 12800);
        uint32_t* BL = (uint32_t*)(dsm + s * P3_ST + 23040);
        #pragma unroll
        for (int it = 0; it < 4; it++) {
            int idx = tid + it * 256;
            int d = idx >> 3, c4 = (idx & 7) * 4;
            uint32_t h0, l0, h1, l1;
            bsplit2(vb[it].x, vb[it].y, h0, l0);
            bsplit2(vb[it].z, vb[it].w, h1, l1);
            int w0 = d * 20 + (c4 >> 1);
            BH[w0] = h0; BH[w0 + 1] = h1;
            BL[w0] = l0; BL[w0 + 1] = l1;
        }
    };

    float acc[5][2][4];
    #pragma unroll
    for (int mt = 0; mt < 5; mt++)
        #pragma unroll
        for (int nt = 0; nt < 2; nt++)
            #pragma unroll
            for (int q = 0; q < 4; q++) acc[mt][nt][q] = 0.f;

    // prologue: chunk 0
    stage_a(0, 0);
    load_b(0);
    store_b(0);
    cp_wait0();
    __syncthreads();

    const int n0 = wid * 16;
    const uint32_t aoffb = (uint32_t)((lane & 15) * 80 + (lane >> 4) * 16);
    const uint32_t boff0 = (uint32_t)((n0 + ((lane >> 4) & 1) * 8 + (lane & 7)) * 80
                                      + ((lane >> 3) & 1) * 16);

    for (int c = 0; c < 8; c++) {
        const int s = c & 1;
        if (c < 7) { stage_a(c + 1, s ^ 1); load_b(c + 1); }
        // ---- mma on stage s (interleaved accumulators) -------------------
        {
            const uint32_t pAH = sbase + s * P3_ST;
            const uint32_t pAL = pAH + 6400;
            const uint32_t pBH = pAH + 12800;
            const uint32_t pBL = pAH + 23040;
            #pragma unroll
            for (int ks = 0; ks < 2; ks++) {
                uint32_t bh0, bh1, bh2, bh3, bl0, bl1, bl2, bl3;
                ldm_x4(bh0, bh1, bh2, bh3, pBH + boff0 + ks * 32);
                ldm_x4(bl0, bl1, bl2, bl3, pBL + boff0 + ks * 32);
                #pragma unroll
                for (int mt = 0; mt < 5; mt++) {
                    uint32_t ah0, ah1, ah2, ah3, al0, al1, al2, al3;
                    uint32_t ao = aoffb + (uint32_t)(mt * 16 * 80 + ks * 32);
                    ldm_x4(ah0, ah1, ah2, ah3, pAH + ao);
                    ldm_x4(al0, al1, al2, al3, pAL + ao);
                    mma_bf16(acc[mt][0], ah0, ah1, ah2, ah3, bh0, bh1);
                    mma_bf16(acc[mt][1], ah0, ah1, ah2, ah3, bh2, bh3);
                    mma_bf16(acc[mt][0], ah0, ah1, ah2, ah3, bl0, bl1);
                    mma_bf16(acc[mt][1], ah0, ah1, ah2, ah3, bl2, bl3);
                    mma_bf16(acc[mt][0], al0, al1, al2, al3, bh0, bh1);
                    mma_bf16(acc[mt][1], al0, al1, al2, al3, bh2, bh3);
                }
            }
        }
        if (c < 7) { store_b(s ^ 1); cp_wait0(); }
        __syncthreads();
    }
    // ---- epilogue: scale by cinv[t], write split-K partials -----------------
    float* outp = g_vtp + (size_t)kz * 40 * 75 * 256 + (size_t)b * 75 * 256 + nh * 128;
    #pragma unroll
    for (int mt = 0; mt < 5; mt++) {
        int t = mt * 16 + gid;
        #pragma unroll
        for (int nt = 0; nt < 2; nt++) {
            int d = n0 + nt * 8 + tig * 2;
            if (t < 75) {
                float ci = scv[t];
                float2 v0 = {acc[mt][nt][0] * ci, acc[mt][nt][1] * ci};
                *(float2*)(outp + (size_t)t * 256 + d) = v0;
            }
            if (t + 8 < 75) {
                float ci = scv[t + 8];
                float2 v1 = {acc[mt][nt][2] * ci, acc[mt][nt][3] * ci};
                *(float2*)(outp + (size_t)(t + 8) * 256 + d) = v1;
            }
        }
    }
}

// ============ PHASE 4: score1 only (375 blocks) =============================
__global__ void __launch_bounds__(256) k_tail(const float* __restrict__ text) {
    const int tid = threadIdx.x;
    const int lane = tid & 31, w = tid >> 5;
    const int gt = blockIdx.x * 8 + w;
    if (gt < 3000) {
        const int b = gt / 75, t = gt % 75, blk = b / 5;
        const size_t SL = (size_t)40 * 75 * 256;
        const size_t voff = ((size_t)b * 75 + t) * 256;
        const float* e = text + ((size_t)blk * 75 + t) * 256;
        float dot = 0.f, nv = 0.f, ne = 0.f;
        #pragma unroll
        for (int j = 0; j < 8; j++) {
            int d = lane + 32 * j;
            float a = 0.f;
            #pragma unroll
            for (int s8 = 0; s8 < 8; s8++) a += g_vtp[s8 * SL + voff + d];
            float cc = e[d];
            dot = fmaf(a, cc, dot); nv = fmaf(a, a, nv); ne = fmaf(cc, cc, ne);
        }
        #pragma unroll
        for (int o = 16; o > 0; o >>= 1) {
            dot += __shfl_xor_sync(0xffffffffu, dot, o);
            nv  += __shfl_xor_sync(0xffffffffu, nv,  o);
            ne  += __shfl_xor_sync(0xffffffffu, ne,  o);
        }
        if (lane == 0)
            g_el[b * 75 + t] = __expf(dot / (fmaxf(sqrtf(nv), 1e-12f) * fmaxf(sqrtf(ne), 1e-12f)));
    }
}

// ============ PHASE 5: final scalar =========================================
__global__ void k_final(float* __restrict__ out) {
    const int tid = threadIdx.x;
    __shared__ float lsm[200];
    __shared__ float bscore[8];
    if (tid < 200) {
        int blk = tid / 25, rem = tid % 25, i = rem / 5, sb = rem % 5;
        int gi = blk * 5 + i;
        float s2 = 0.f;
        #pragma unroll
        for (int m = 0; m < 8; m++) s2 += __expf(g_logit2[((size_t)gi * 8 + m) * 5 + sb]);
        float s1 = 0.f;
        #pragma unroll
        for (int l = 0; l < 15; l++) s1 += g_el[gi * 75 + sb * 15 + l];
        float l1 = __logf(__powf(s1, 0.2f) + EPSL);
        float l2 = __logf(__powf(s2, 0.2f) + EPSL);
        lsm[tid] = 10.0f * (l1 + l2);
    }
    __syncthreads();
    if (tid < 8) {
        const float* L = lsm + tid * 25;
        float rows[5] = {0, 0, 0, 0, 0}, cols[5] = {0, 0, 0, 0, 0};
        for (int i = 0; i < 5; i++)
            for (int sb = 0; sb < 5; sb++) {
                rows[i] += L[i * 5 + sb];
                cols[sb] += L[i * 5 + sb];
            }
        float acc = 0.f;
        for (int i = 0; i < 5; i++) {
            float dg = L[i * 5 + i];
            acc += -__logf(dg / rows[i] + EPSL) - __logf(dg / cols[i] + EPSL);
        }
        float reg = 0.f;
        for (int i = 0; i < 5; i++) reg += g_regval[tid * 5 + i];
        bscore[tid] = acc / 5.0f + reg / 5.0f;
    }
    __syncthreads();
    if (tid == 0) {
        float tot = 0.f;
        for (int k = 0; k < 8; k++) tot += bscore[k];
        out[0] = tot / 9.0f;
    }
}

// ---------------- launch -----------------------------------------------------
extern "C" void kernel_launch(void* const* d_in, const int* in_sizes, int n_in,
                              void* d_out, int out_size) {
    (void)in_sizes; (void)n_in; (void)out_size;
    const float* image = (const float*)d_in[0];
    const float* text  = (const float*)d_in[1];
    float* out = (float*)d_out;

    cudaFuncSetAttribute(k_phase1, cudaFuncAttributeMaxDynamicSharedMemorySize, P1_SZ);
    cudaFuncSetAttribute(k_vtidal, cudaFuncAttributeMaxDynamicSharedMemorySize, P3_SZ);

    k_prep<<<300, 256>>>(text);
    k_phase1<<<960, 256, P1_SZ>>>(image, text);
    k_colstats<<<3000, 256>>>();
    k_vtidal<<<1000, 256, P3_SZ>>>(image, text);
    k_tail<<<375, 256>>>(text);
    k_final<<<1, 256>>>(out);
}